// round 2
// baseline (speedup 1.0000x reference)
#include <cuda_runtime.h>

// Fixed shapes per reference: B=4096, IN=HID=8192, fp32
#define IN_DIM   8192
#define HID_DIM  8192
#define COL4     (IN_DIM / 4)            // 2048 float4 per row
#define ROW_CHUNKS 64                    // y-blocks in colsum
#define ROWS_PER_CHUNK (HID_DIM / ROW_CHUNKS)   // 128
#define CS_BLK_X (COL4 / 256)            // 8 column groups of 256 float4

// Device-global scratch (allocation-free rule: device globals allowed)
__device__ float    g_partial[ROW_CHUNKS * IN_DIM];   // 2 MB
__device__ float    g_wsum[IN_DIM];                   // 32 KB
__device__ unsigned g_ctr[CS_BLK_X];                  // zero-init; self-resetting via wrap

// Kernel 1: partial column sums of W [HID, IN] + fused final reduction.
// grid = (8, 64), block = 256. Each thread owns one float4 column lane,
// sums 128 rows. The LAST block to finish within a column group (blockIdx.x)
// reduces the 64 partials for that slice into g_wsum (fixed order -> deterministic).
__global__ __launch_bounds__(256) void colsum_fused(const float* __restrict__ w) {
    const int t    = threadIdx.x;
    const int col4 = blockIdx.x * 256 + t;              // 0..2047
    const int r0   = blockIdx.y * ROWS_PER_CHUNK;
    const float4* __restrict__ w4 = reinterpret_cast<const float4*>(w);

    float4 acc = make_float4(0.f, 0.f, 0.f, 0.f);
    #pragma unroll 8
    for (int r = 0; r < ROWS_PER_CHUNK; ++r) {
        float4 v = __ldcs(&w4[(size_t)(r0 + r) * COL4 + col4]);  // streaming, evict-first
        acc.x += v.x; acc.y += v.y; acc.z += v.z; acc.w += v.w;
    }
    reinterpret_cast<float4*>(g_partial)[(size_t)blockIdx.y * COL4 + col4] = acc;

    // Make this thread's partial visible GPU-wide, then elect the last block
    // of this column group to perform the reduction.
    __threadfence();
    __syncthreads();

    __shared__ unsigned s_last;
    if (t == 0) {
        unsigned prev = atomicInc(&g_ctr[blockIdx.x], ROW_CHUNKS - 1); // wraps to 0
        s_last = (prev == ROW_CHUNKS - 1);
    }
    __syncthreads();

    if (s_last) {
        __threadfence();  // acquire: see all blocks' partials
        const float4* __restrict__ p4 = reinterpret_cast<const float4*>(g_partial);
        float4 s = make_float4(0.f, 0.f, 0.f, 0.f);
        #pragma unroll 8
        for (int c = 0; c < ROW_CHUNKS; ++c) {          // fixed order -> deterministic
            float4 v = p4[(size_t)c * COL4 + col4];
            s.x += v.x; s.y += v.y; s.z += v.z; s.w += v.w;
        }
        reinterpret_cast<float4*>(g_wsum)[col4] = s;
    }
}

// Kernel 2: out[b] = 0.75 * dot(x[b], g_wsum). One WARP per batch row.
// 64 float4 per lane of pure streaming, shuffle-only reduction.
__global__ __launch_bounds__(256) void rowdot(const float* __restrict__ x,
                                              float* __restrict__ out, int B) {
    const int lane = threadIdx.x & 31;
    const int row  = blockIdx.x * 8 + (threadIdx.x >> 5);
    if (row >= B) return;

    const float4* __restrict__ x4 =
        reinterpret_cast<const float4*>(x + (size_t)row * IN_DIM);
    const float4* __restrict__ w4 = reinterpret_cast<const float4*>(g_wsum);

    float acc = 0.f;
    // 2048 float4 per row / 32 lanes = 64 per lane; unroll 4 -> 8 LDG.128 in flight
    #pragma unroll 4
    for (int k = 0; k < COL4 / 32; ++k) {
        const int i = lane + (k << 5);
        float4 xv = __ldcs(&x4[i]);     // streaming (no reuse)
        float4 wv = __ldg(&w4[i]);      // L2-resident, shared by all warps
        acc = fmaf(xv.x, wv.x, acc);
        acc = fmaf(xv.y, wv.y, acc);
        acc = fmaf(xv.z, wv.z, acc);
        acc = fmaf(xv.w, wv.w, acc);
    }

    #pragma unroll
    for (int off = 16; off > 0; off >>= 1)
        acc += __shfl_xor_sync(0xFFFFFFFFu, acc, off);

    if (lane == 0) out[row] = acc * 0.75f;   // (/2) * 1.5
}

extern "C" void kernel_launch(void* const* d_in, const int* in_sizes, int n_in,
                              void* d_out, int out_size) {
    const float* x = (const float*)d_in[0];   // [B, IN]
    const float* w = (const float*)d_in[1];   // [HID, IN]
    float* out = (float*)d_out;               // [B, 1]
    const int B = in_sizes[0] / IN_DIM;

    dim3 g1(CS_BLK_X, ROW_CHUNKS);
    colsum_fused<<<g1, 256>>>(w);
    rowdot<<<(B + 7) / 8, 256>>>(x, out, B);
}